// round 1
// baseline (speedup 1.0000x reference)
#include <cuda_runtime.h>
#include <math_constants.h>

#define N_PTS   92160
#define D_DIM   192
#define BD_DIM  256
#define H_HEADS 8
#define FF_DIM  768
#define S_SETS  2560
#define L_LEN   36
#define M_BOX   256
#define HD_DIM  24

// ---------------- scratch (static device globals; no allocation) ----------------
__device__ float g_q[N_PTS * D_DIM];
__device__ float g_ctx[N_PTS * D_DIM];
__device__ float g_proj[N_PTS * D_DIM];
__device__ float g_x[N_PTS * D_DIM];
__device__ float g_y[N_PTS * D_DIM];
__device__ float g_h[(size_t)N_PTS * FF_DIM];
__device__ float g_k[M_BOX * D_DIM];
__device__ float g_v[M_BOX * D_DIM];
__device__ int   g_fp[N_PTS];

// ---------------- generic C = A @ W^T + bias GEMM ----------------
// A: (Mrows, K) row-major, W: (Dout, K) row-major, C: (Mrows, Dout)
// Requirements: Mrows % 128 == 0, Dout % 64 == 0, K % 16 == 0  (all shapes here satisfy this)
#define BM 128
#define BN 64
#define BK 16

template<bool RELU, bool ADD2>
__global__ __launch_bounds__(256, 2)
void gemm_kernel(const float* __restrict__ A, const float* __restrict__ A2,
                 const float* __restrict__ W, const float* __restrict__ bias,
                 float* __restrict__ C, int K, int Dout)
{
    __shared__ float As[BK][BM + 4];
    __shared__ float Ws[BK][BN + 4];

    const int tid = threadIdx.x;
    const int tx = tid & 15;          // n direction (16 * 4 = 64)
    const int ty = tid >> 4;          // m direction (16 * 8 = 128)
    const int m0 = blockIdx.y * BM;
    const int n0 = blockIdx.x * BN;

    const int ar = tid >> 2;          // 0..63
    const int ac = (tid & 3) << 2;    // 0,4,8,12

    const float* Ap0  = A  + (size_t)(m0 + ar)      * K + ac;
    const float* Ap1  = A  + (size_t)(m0 + ar + 64) * K + ac;
    const float* A2p0 = ADD2 ? (A2 + (size_t)(m0 + ar)      * K + ac) : nullptr;
    const float* A2p1 = ADD2 ? (A2 + (size_t)(m0 + ar + 64) * K + ac) : nullptr;
    const float* Wp   = W  + (size_t)(n0 + ar)      * K + ac;

    const int nT = K / BK;

    float4 pa0 = *(const float4*)(Ap0);
    float4 pa1 = *(const float4*)(Ap1);
    float4 pw  = *(const float4*)(Wp);
    if (ADD2) {
        float4 q0 = *(const float4*)(A2p0);
        float4 q1 = *(const float4*)(A2p1);
        pa0.x += q0.x; pa0.y += q0.y; pa0.z += q0.z; pa0.w += q0.w;
        pa1.x += q1.x; pa1.y += q1.y; pa1.z += q1.z; pa1.w += q1.w;
    }

    float acc[8][4];
    #pragma unroll
    for (int i = 0; i < 8; i++)
        #pragma unroll
        for (int j = 0; j < 4; j++) acc[i][j] = 0.f;

    for (int t = 0; t < nT; ++t) {
        As[ac+0][ar]      = pa0.x; As[ac+1][ar]      = pa0.y;
        As[ac+2][ar]      = pa0.z; As[ac+3][ar]      = pa0.w;
        As[ac+0][ar+64]   = pa1.x; As[ac+1][ar+64]   = pa1.y;
        As[ac+2][ar+64]   = pa1.z; As[ac+3][ar+64]   = pa1.w;
        Ws[ac+0][ar]      = pw.x;  Ws[ac+1][ar]      = pw.y;
        Ws[ac+2][ar]      = pw.z;  Ws[ac+3][ar]      = pw.w;
        __syncthreads();

        if (t + 1 < nT) {
            const int off = (t + 1) * BK;
            pa0 = *(const float4*)(Ap0 + off);
            pa1 = *(const float4*)(Ap1 + off);
            pw  = *(const float4*)(Wp  + off);
            if (ADD2) {
                float4 q0 = *(const float4*)(A2p0 + off);
                float4 q1 = *(const float4*)(A2p1 + off);
                pa0.x += q0.x; pa0.y += q0.y; pa0.z += q0.z; pa0.w += q0.w;
                pa1.x += q1.x; pa1.y += q1.y; pa1.z += q1.z; pa1.w += q1.w;
            }
        }

        #pragma unroll
        for (int k = 0; k < BK; ++k) {
            float a[8], w[4];
            #pragma unroll
            for (int i = 0; i < 8; i++) a[i] = As[k][ty * 8 + i];
            #pragma unroll
            for (int j = 0; j < 4; j++) w[j] = Ws[k][tx * 4 + j];
            #pragma unroll
            for (int i = 0; i < 8; i++)
                #pragma unroll
                for (int j = 0; j < 4; j++) acc[i][j] += a[i] * w[j];
        }
        __syncthreads();
    }

    const float b0 = bias[n0 + tx*4 + 0];
    const float b1 = bias[n0 + tx*4 + 1];
    const float b2 = bias[n0 + tx*4 + 2];
    const float b3 = bias[n0 + tx*4 + 3];
    #pragma unroll
    for (int i = 0; i < 8; i++) {
        float4 o;
        o.x = acc[i][0] + b0; o.y = acc[i][1] + b1;
        o.z = acc[i][2] + b2; o.w = acc[i][3] + b3;
        if (RELU) {
            o.x = fmaxf(o.x, 0.f); o.y = fmaxf(o.y, 0.f);
            o.z = fmaxf(o.z, 0.f); o.w = fmaxf(o.w, 0.f);
        }
        *(float4*)(C + (size_t)(m0 + ty*8 + i) * Dout + n0 + tx*4) = o;
    }
}

// ---------------- fused attention: one CTA per (set, head) ----------------
// smem: qs[36*24] | vs[256*24] | sc[36*256] | qb[36]
#define ATTN_SMEM ((L_LEN*HD_DIM + M_BOX*HD_DIM + L_LEN*M_BOX) * 4 + L_LEN * 4)

__global__ __launch_bounds__(256)
void attn_kernel(const float* __restrict__ qbuf, const float* __restrict__ kbuf,
                 const float* __restrict__ vbuf, const int* __restrict__ vinds,
                 const int* __restrict__ vcoords, const int* __restrict__ bcoords,
                 float* __restrict__ ctxbuf)
{
    extern __shared__ float sm[];
    float* qs = sm;                              // 36*24
    float* vs = qs + L_LEN * HD_DIM;             // 256*24
    float* sc = vs + M_BOX * HD_DIM;             // 36*256
    int*   qb = (int*)(sc + L_LEN * M_BOX);      // 36

    const int s = blockIdx.x;
    const int h = blockIdx.y;
    const int t = threadIdx.x;                   // t == box index m

    // K row for this thread's box -> registers; V row -> smem
    float kr[HD_DIM];
    {
        const float4* kp = (const float4*)(kbuf + (size_t)t * D_DIM + h * HD_DIM);
        const float4* vp = (const float4*)(vbuf + (size_t)t * D_DIM + h * HD_DIM);
        #pragma unroll
        for (int i = 0; i < 6; i++) {
            float4 f = kp[i];
            kr[4*i+0] = f.x; kr[4*i+1] = f.y; kr[4*i+2] = f.z; kr[4*i+3] = f.w;
            float4 g = vp[i];
            vs[t*HD_DIM + 4*i + 0] = g.x; vs[t*HD_DIM + 4*i + 1] = g.y;
            vs[t*HD_DIM + 4*i + 2] = g.z; vs[t*HD_DIM + 4*i + 3] = g.w;
        }
    }
    const int bb = bcoords[t * 4];

    if (t < L_LEN) qb[t] = vcoords[(size_t)vinds[s * L_LEN + t] * 4];
    for (int i = t; i < L_LEN * HD_DIM; i += 256) {
        int l = i / HD_DIM, dd = i % HD_DIM;
        qs[i] = qbuf[(size_t)vinds[s * L_LEN + l] * D_DIM + h * HD_DIM + dd];
    }
    __syncthreads();

    // scores: thread t owns column m = t
    const float scale = 0.20412414523193154f;    // 1/sqrt(24)
    #pragma unroll 2
    for (int l = 0; l < L_LEN; l++) {
        const float* qr = qs + l * HD_DIM;
        float dot = 0.f;
        #pragma unroll
        for (int j = 0; j < HD_DIM; j++) dot += qr[j] * kr[j];
        sc[l * M_BOX + t] = (qb[l] != bb) ? -CUDART_INF_F : dot * scale;
    }
    __syncthreads();

    // softmax: warp per row
    const int w = t >> 5, lane = t & 31;
    for (int l = w; l < L_LEN; l += 8) {
        float* row = sc + l * M_BOX;
        float e[8];
        float mx = -CUDART_INF_F;
        #pragma unroll
        for (int i = 0; i < 8; i++) { e[i] = row[lane + 32*i]; mx = fmaxf(mx, e[i]); }
        #pragma unroll
        for (int o = 16; o > 0; o >>= 1) mx = fmaxf(mx, __shfl_xor_sync(0xffffffffu, mx, o));
        float sum = 0.f;
        if (mx > -CUDART_INF_F) {
            #pragma unroll
            for (int i = 0; i < 8; i++) { e[i] = __expf(e[i] - mx); sum += e[i]; }
        } else {
            #pragma unroll
            for (int i = 0; i < 8; i++) e[i] = 0.f;   // fully-masked row -> zeros (bo==0 path)
        }
        #pragma unroll
        for (int o = 16; o > 0; o >>= 1) sum += __shfl_xor_sync(0xffffffffu, sum, o);
        const float inv = sum > 0.f ? 1.0f / sum : 0.f;
        #pragma unroll
        for (int i = 0; i < 8; i++) row[lane + 32*i] = e[i] * inv;
    }
    __syncthreads();

    // ctx: warp w handles rows w, w+8, w+16, w+24 (+ w+32 for w<4); lanes 0..23 = d
    if (lane < HD_DIM) {
        const float* s0 = sc + (w +  0) * M_BOX;
        const float* s1 = sc + (w +  8) * M_BOX;
        const float* s2 = sc + (w + 16) * M_BOX;
        const float* s3 = sc + (w + 24) * M_BOX;
        const bool has5 = (w < L_LEN - 32);
        const float* s4 = has5 ? (sc + (w + 32) * M_BOX) : s0;
        float a0 = 0.f, a1 = 0.f, a2 = 0.f, a3 = 0.f, a4 = 0.f;
        #pragma unroll 2
        for (int m = 0; m < M_BOX; m++) {
            const float vv = vs[m * HD_DIM + lane];
            a0 += s0[m] * vv;
            a1 += s1[m] * vv;
            a2 += s2[m] * vv;
            a3 += s3[m] * vv;
            if (has5) a4 += s4[m] * vv;
        }
        const size_t base = (size_t)s * L_LEN;
        const int    off  = h * HD_DIM + lane;
        ctxbuf[(base + w +  0) * D_DIM + off] = a0;
        ctxbuf[(base + w +  8) * D_DIM + off] = a1;
        ctxbuf[(base + w + 16) * D_DIM + off] = a2;
        ctxbuf[(base + w + 24) * D_DIM + off] = a3;
        if (has5) ctxbuf[(base + w + 32) * D_DIM + off] = a4;
    }
}

// ---------------- first-occurrence scatter index ----------------
__global__ void init_fp_kernel(int* __restrict__ fp)
{
    int i = blockIdx.x * blockDim.x + threadIdx.x;
    if (i < N_PTS) fp[i] = 0x7FFFFFFF;
}

__global__ void fill_fp_kernel(const int* __restrict__ vinds, int* __restrict__ fp)
{
    int p = blockIdx.x * blockDim.x + threadIdx.x;
    if (p < S_SETS * L_LEN) {
        int n = vinds[p];
        if (n >= 0 && n < N_PTS) atomicMin(&fp[n], p);
    }
}

// ---------------- residual + layernorm (warp per row) ----------------
template<bool GATHER>
__global__ __launch_bounds__(256)
void ln_kernel(const float* __restrict__ a, const float* __restrict__ b,
               const int* __restrict__ fp, const float* __restrict__ gamma,
               const float* __restrict__ beta, float* __restrict__ outp)
{
    const int row  = (blockIdx.x * 256 + threadIdx.x) >> 5;
    const int lane = threadIdx.x & 31;
    if (row >= N_PTS) return;

    const float* arow = a + (size_t)row * D_DIM;
    const float* brow;
    if (GATHER) {
        int p = fp[row];
        if (p < 0 || p >= N_PTS) p = row;   // defensive; never triggers for valid inputs
        brow = b + (size_t)p * D_DIM;
    } else {
        brow = b + (size_t)row * D_DIM;
    }

    float v[6];
    float s = 0.f;
    #pragma unroll
    for (int i = 0; i < 6; i++) {
        const int idx = lane + 32 * i;
        v[i] = arow[idx] + brow[idx];
        s += v[i];
    }
    #pragma unroll
    for (int o = 16; o > 0; o >>= 1) s += __shfl_xor_sync(0xffffffffu, s, o);
    const float mean = s * (1.0f / D_DIM);

    float q = 0.f;
    #pragma unroll
    for (int i = 0; i < 6; i++) { const float d = v[i] - mean; q += d * d; }
    #pragma unroll
    for (int o = 16; o > 0; o >>= 1) q += __shfl_xor_sync(0xffffffffu, q, o);
    const float inv = rsqrtf(q * (1.0f / D_DIM) + 1e-5f);

    float* orow = outp + (size_t)row * D_DIM;
    #pragma unroll
    for (int i = 0; i < 6; i++) {
        const int idx = lane + 32 * i;
        orow[idx] = (v[i] - mean) * inv * gamma[idx] + beta[idx];
    }
}

// ---------------- launch ----------------
extern "C" void kernel_launch(void* const* d_in, const int* in_sizes, int n_in,
                              void* d_out, int out_size)
{
    const float* src     = (const float*)d_in[0];
    const float* pos     = (const float*)d_in[1];
    const float* boxf    = (const float*)d_in[2];
    const float* boxp    = (const float*)d_in[3];
    const int*   vcoords = (const int*)  d_in[4];
    const int*   bcoords = (const int*)  d_in[5];
    const int*   vinds   = (const int*)  d_in[6];
    const float* Wq = (const float*)d_in[7];  const float* bq  = (const float*)d_in[8];
    const float* Wk = (const float*)d_in[9];  const float* bk  = (const float*)d_in[10];
    const float* Wv = (const float*)d_in[11]; const float* bv  = (const float*)d_in[12];
    const float* Wo = (const float*)d_in[13]; const float* bo  = (const float*)d_in[14];
    const float* W1 = (const float*)d_in[15]; const float* b1  = (const float*)d_in[16];
    const float* W2 = (const float*)d_in[17]; const float* b2  = (const float*)d_in[18];
    const float* g1 = (const float*)d_in[19]; const float* be1 = (const float*)d_in[20];
    const float* g2 = (const float*)d_in[21]; const float* be2 = (const float*)d_in[22];
    float* out = (float*)d_out;

    float *qb, *ctxb, *projb, *xb, *yb, *hb, *kb, *vb;
    int* fpb;
    cudaGetSymbolAddress((void**)&qb,    g_q);
    cudaGetSymbolAddress((void**)&ctxb,  g_ctx);
    cudaGetSymbolAddress((void**)&projb, g_proj);
    cudaGetSymbolAddress((void**)&xb,    g_x);
    cudaGetSymbolAddress((void**)&yb,    g_y);
    cudaGetSymbolAddress((void**)&hb,    g_h);
    cudaGetSymbolAddress((void**)&kb,    g_k);
    cudaGetSymbolAddress((void**)&vb,    g_v);
    cudaGetSymbolAddress((void**)&fpb,   g_fp);

    cudaFuncSetAttribute(attn_kernel, cudaFuncAttributeMaxDynamicSharedMemorySize, ATTN_SMEM);

    const int rowBlocks = N_PTS / BM;        // 720

    // K = (box_feature + box_pos) @ Wk^T + bk ; V = box_feature @ Wv^T + bv
    gemm_kernel<false, true ><<<dim3(D_DIM/BN,  M_BOX/BM), 256>>>(boxf, boxp,    Wk, bk, kb,    BD_DIM, D_DIM);
    gemm_kernel<false, false><<<dim3(D_DIM/BN,  M_BOX/BM), 256>>>(boxf, nullptr, Wv, bv, vb,    BD_DIM, D_DIM);
    // Q = (src + pos) @ Wq^T + bq
    gemm_kernel<false, true ><<<dim3(D_DIM/BN,  rowBlocks), 256>>>(src,  pos,    Wq, bq, qb,    D_DIM,  D_DIM);
    // fused masked attention
    attn_kernel<<<dim3(S_SETS, H_HEADS), 256, ATTN_SMEM>>>(qb, kb, vb, vinds, vcoords, bcoords, ctxb);
    // O projection
    gemm_kernel<false, false><<<dim3(D_DIM/BN,  rowBlocks), 256>>>(ctxb, nullptr, Wo, bo, projb, D_DIM, D_DIM);
    // first-occurrence scatter index
    init_fp_kernel<<<N_PTS / 256, 256>>>(fpb);
    fill_fp_kernel<<<(S_SETS * L_LEN) / 256, 256>>>(vinds, fpb);
    // x = LN(src + proj[first_pos])
    ln_kernel<true ><<<N_PTS / 8, 256>>>(src, projb, fpb, g1, be1, xb);
    // FFN
    gemm_kernel<true,  false><<<dim3(FF_DIM/BN, rowBlocks), 256>>>(xb, nullptr, W1, b1, hb, D_DIM,  FF_DIM);
    gemm_kernel<false, false><<<dim3(D_DIM/BN,  rowBlocks), 256>>>(hb, nullptr, W2, b2, yb, FF_DIM, D_DIM);
    // out = LN(x + ffn)
    ln_kernel<false><<<N_PTS / 8, 256>>>(xb, yb, nullptr, g2, be2, out);
}